// round 2
// baseline (speedup 1.0000x reference)
#include <cuda_runtime.h>
#include <cstdint>

// KVDequantizer: Q4 nibble unpack + per-block(32) scale/bias.
// Inputs (metadata order):
//   d_in[0] k_packed int32 [2, 131072, 16]
//   d_in[1] k_scale  f32   [2, 131072, 1]
//   d_in[2] k_bias   f32   [2, 131072, 1]
//   d_in[3] v_packed int32 [2, 131072, 16]
//   d_in[4] v_scale  f32   [2, 131072, 1]
//   d_in[5] v_bias   f32   [2, 131072, 1]
// Output: [k_flat (8388608 f32) | v_flat (8388608 f32)]
//
// One thread = one float4 of output = one int2 of packed input.
// Per-tensor int2 count: 2*131072*16/2 = 2,097,152.

static constexpr int N_INT2_PER_TENSOR = 2 * 131072 * 16 / 2;  // 2,097,152

__global__ __launch_bounds__(256) void kv_dequant_kernel(
    const int2* __restrict__ kp, const float* __restrict__ ks, const float* __restrict__ kb,
    const int2* __restrict__ vp, const float* __restrict__ vs, const float* __restrict__ vb,
    float4* __restrict__ out)
{
    int i = blockIdx.x * blockDim.x + threadIdx.x;

    const int2* p;
    const float* s;
    const float* b;
    float4* o;
    int j;

    if (i < N_INT2_PER_TENSOR) {
        p = kp; s = ks; b = kb; o = out; j = i;
    } else {
        p = vp; s = vs; b = vb; o = out + N_INT2_PER_TENSOR; j = i - N_INT2_PER_TENSOR;
    }

    int2 x = __ldg(p + j);
    int blk = j >> 3;            // 8 int2 per 32-element block
    float sc = __ldg(s + blk);
    float bi = __ldg(b + blk);

    float4 r;
    r.x = (float)( x.x        & 15) * sc + bi;
    r.y = (float)((x.x >> 4)  & 15) * sc + bi;
    r.z = (float)( x.y        & 15) * sc + bi;
    r.w = (float)((x.y >> 4)  & 15) * sc + bi;

    o[j] = r;
}

extern "C" void kernel_launch(void* const* d_in, const int* in_sizes, int n_in,
                              void* d_out, int out_size)
{
    const int2*  kp = (const int2*) d_in[0];
    const float* ks = (const float*)d_in[1];
    const float* kb = (const float*)d_in[2];
    const int2*  vp = (const int2*) d_in[3];
    const float* vs = (const float*)d_in[4];
    const float* vb = (const float*)d_in[5];
    float4* out = (float4*)d_out;

    const int total_threads = 2 * N_INT2_PER_TENSOR;   // 4,194,304
    const int block = 256;
    const int grid = (total_threads + block - 1) / block;  // 16384

    kv_dequant_kernel<<<grid, block>>>(kp, ks, kb, vp, vs, vb, out);
}

// round 3
// speedup vs baseline: 1.0977x; 1.0977x over previous
#include <cuda_runtime.h>
#include <cstdint>

// KVDequantizer: Q4 nibble unpack + per-block(32) scale/bias.
// Inputs (metadata order):
//   d_in[0] k_packed int32 [2, 131072, 16]
//   d_in[1] k_scale  f32   [2, 131072, 1]
//   d_in[2] k_bias   f32   [2, 131072, 1]
//   d_in[3] v_packed int32 [2, 131072, 16]
//   d_in[4] v_scale  f32   [2, 131072, 1]
//   d_in[5] v_bias   f32   [2, 131072, 1]
// Output: [k_flat (8388608 f32) | v_flat (8388608 f32)]
//
// One thread = one int4 (16 B packed = 8 nibble-pairs) -> 2x float4 (32 B out).
// 4 int4 per 32-element quant block -> blk = j >> 2.

static constexpr int N_INT4_PER_TENSOR = 2 * 131072 * 16 / 4;  // 1,048,576

__global__ __launch_bounds__(256) void kv_dequant_kernel(
    const int4* __restrict__ kp, const float* __restrict__ ks, const float* __restrict__ kb,
    const int4* __restrict__ vp, const float* __restrict__ vs, const float* __restrict__ vb,
    float4* __restrict__ out)
{
    int i = blockIdx.x * blockDim.x + threadIdx.x;

    const int4* p;
    const float* s;
    const float* b;
    float4* o;
    int j;

    if (i < N_INT4_PER_TENSOR) {
        p = kp; s = ks; b = kb; o = out; j = i;
    } else {
        p = vp; s = vs; b = vb;
        o = out + 2 * N_INT4_PER_TENSOR;          // float4 offset of v region
        j = i - N_INT4_PER_TENSOR;
    }

    // Read-once packed data: streaming (evict-first) to keep L2 for scale/bias.
    int4 x = __ldcs(p + j);

    int blk = j >> 2;                              // 4 int4 per 32-elem block
    float sc = __ldg(s + blk);
    float bi = __ldg(b + blk);

    float4 r0, r1;
    r0.x = (float)( x.x       & 15) * sc + bi;
    r0.y = (float)((x.x >> 4) & 15) * sc + bi;
    r0.z = (float)( x.y       & 15) * sc + bi;
    r0.w = (float)((x.y >> 4) & 15) * sc + bi;
    r1.x = (float)( x.z       & 15) * sc + bi;
    r1.y = (float)((x.z >> 4) & 15) * sc + bi;
    r1.z = (float)( x.w       & 15) * sc + bi;
    r1.w = (float)((x.w >> 4) & 15) * sc + bi;

    // Write-once output: streaming stores, don't pollute L2.
    __stcs(o + 2 * j,     r0);
    __stcs(o + 2 * j + 1, r1);
}

extern "C" void kernel_launch(void* const* d_in, const int* in_sizes, int n_in,
                              void* d_out, int out_size)
{
    const int4*  kp = (const int4*) d_in[0];
    const float* ks = (const float*)d_in[1];
    const float* kb = (const float*)d_in[2];
    const int4*  vp = (const int4*) d_in[3];
    const float* vs = (const float*)d_in[4];
    const float* vb = (const float*)d_in[5];
    float4* out = (float4*)d_out;

    const int total_threads = 2 * N_INT4_PER_TENSOR;   // 2,097,152
    const int block = 256;
    const int grid = total_threads / block;            // 8192

    kv_dequant_kernel<<<grid, block>>>(kp, ks, kb, vp, vs, vb, out);
}